// round 2
// baseline (speedup 1.0000x reference)
#include <cuda_runtime.h>
#include <cuda_bf16.h>
#include <math.h>

// Problem constants
#define B_SZ    4
#define T_SZ    2048
#define D_SZ    2048
#define H_SZ    16
#define DH_SZ   128
#define M_ROWS  (B_SZ * T_SZ)        // 8192

// ---------------- scratch (no-alloc rule: __device__ globals) ----------------
__device__ float g_q[(size_t)B_SZ * H_SZ * T_SZ * DH_SZ];   // [B,H,T,Dh]
__device__ float g_k[(size_t)B_SZ * H_SZ * T_SZ * DH_SZ];
__device__ float g_v[(size_t)B_SZ * H_SZ * T_SZ * DH_SZ];
__device__ float g_ctx[(size_t)B_SZ * T_SZ * D_SZ];         // [B,T,D]

// ================= GEMM: C[m,n] = sum_k A[m,k]*W[n,k] + bias[n] ==============
// Block tile 128(M) x 64(N), BK=16, 256 threads, 8x4 micro-tile.
// Software-pipelined: global->register prefetch overlaps the FFMA mainloop.
// headMajor==1: write C at [((b*H + n/128)*T + t)*128 + n%128]
#define BM 128
#define BN 64
#define BK 16
#define TM 8
#define TN 4

__global__ __launch_bounds__(256, 4)
void gemm_bias(const float* __restrict__ A, const float* __restrict__ W,
               const float* __restrict__ bias, float* __restrict__ C,
               int headMajor)
{
    __shared__ float As[BK][BM + 4];   // transposed: As[k][m]
    __shared__ float Bs[BK][BN + 4];   // transposed: Bs[k][n]

    const int tid = threadIdx.x;
    const int tx = tid & 15;           // N direction
    const int ty = tid >> 4;           // M direction
    const int m0 = blockIdx.y * BM;
    const int n0 = blockIdx.x * BN;

    const float* Ablk = A + (size_t)m0 * D_SZ;
    const float* Wblk = W + (size_t)n0 * D_SZ;

    // ---- per-thread load coordinates ----
    // A tile: 128x16 = 512 float4, 2 per thread
    const int a_ml0 = tid >> 2;                // 0..63   (lin = tid)
    const int a_ml1 = (tid + 256) >> 2;        // 64..127 (lin = tid+256)
    const int a_k4  = (tid & 3) << 2;          // 0,4,8,12 (same for both)
    // W tile: 64x16 = 256 float4, 1 per thread
    const int w_nl  = tid >> 2;                // 0..63
    const int w_k4  = (tid & 3) << 2;

    float acc[TM][TN];
#pragma unroll
    for (int i = 0; i < TM; i++)
#pragma unroll
        for (int j = 0; j < TN; j++) acc[i][j] = 0.0f;

    // ---- prologue: prefetch k0 = 0 ----
    float4 aReg0 = *reinterpret_cast<const float4*>(Ablk + (size_t)a_ml0 * D_SZ + a_k4);
    float4 aReg1 = *reinterpret_cast<const float4*>(Ablk + (size_t)a_ml1 * D_SZ + a_k4);
    float4 wReg  = *reinterpret_cast<const float4*>(Wblk + (size_t)w_nl  * D_SZ + w_k4);

    for (int k0 = 0; k0 < D_SZ; k0 += BK) {
        // ---- store prefetched tile to smem (transposed) ----
        As[a_k4 + 0][a_ml0] = aReg0.x;
        As[a_k4 + 1][a_ml0] = aReg0.y;
        As[a_k4 + 2][a_ml0] = aReg0.z;
        As[a_k4 + 3][a_ml0] = aReg0.w;
        As[a_k4 + 0][a_ml1] = aReg1.x;
        As[a_k4 + 1][a_ml1] = aReg1.y;
        As[a_k4 + 2][a_ml1] = aReg1.z;
        As[a_k4 + 3][a_ml1] = aReg1.w;
        Bs[w_k4 + 0][w_nl] = wReg.x;
        Bs[w_k4 + 1][w_nl] = wReg.y;
        Bs[w_k4 + 2][w_nl] = wReg.z;
        Bs[w_k4 + 3][w_nl] = wReg.w;
        __syncthreads();

        // ---- prefetch next tile (overlaps with FFMA mainloop below) ----
        const int kn = k0 + BK;
        if (kn < D_SZ) {
            aReg0 = *reinterpret_cast<const float4*>(Ablk + (size_t)a_ml0 * D_SZ + kn + a_k4);
            aReg1 = *reinterpret_cast<const float4*>(Ablk + (size_t)a_ml1 * D_SZ + kn + a_k4);
            wReg  = *reinterpret_cast<const float4*>(Wblk + (size_t)w_nl  * D_SZ + kn + w_k4);
        }

        // ---- FFMA mainloop ----
#pragma unroll
        for (int kk = 0; kk < BK; kk++) {
            float a[TM], b[TN];
            *reinterpret_cast<float4*>(a)     = *reinterpret_cast<const float4*>(&As[kk][ty * TM]);
            *reinterpret_cast<float4*>(a + 4) = *reinterpret_cast<const float4*>(&As[kk][ty * TM + 4]);
            *reinterpret_cast<float4*>(b)     = *reinterpret_cast<const float4*>(&Bs[kk][tx * TN]);
#pragma unroll
            for (int i = 0; i < TM; i++)
#pragma unroll
                for (int j = 0; j < TN; j++)
                    acc[i][j] += a[i] * b[j];
        }
        __syncthreads();
    }

    // ---- epilogue ----
    const int nbase = n0 + tx * TN;
    float bb[TN];
#pragma unroll
    for (int j = 0; j < TN; j++) bb[j] = __ldg(bias + nbase + j);

#pragma unroll
    for (int i = 0; i < TM; i++) {
        int m = m0 + ty * TM + i;
        float4 out;
        out.x = acc[i][0] + bb[0];
        out.y = acc[i][1] + bb[1];
        out.z = acc[i][2] + bb[2];
        out.w = acc[i][3] + bb[3];
        if (headMajor) {
            int b_ = m >> 11;          // / T_SZ
            int t  = m & 2047;
            int h  = nbase >> 7;       // / DH_SZ
            int dh = nbase & 127;
            *reinterpret_cast<float4*>(C + ((((size_t)b_ * H_SZ + h) * T_SZ + t) * DH_SZ + dh)) = out;
        } else {
            *reinterpret_cast<float4*>(C + (size_t)m * D_SZ + nbase) = out;
        }
    }
}

// ===================== Flash attention (fp32, online softmax) ================
// Grid: (T/64 q-tiles, B*H). Block: 256 threads (tx = tid&15 cols, ty = tid>>4 rows).
// S tile 64x64 (4x4 micro), O tile 64x128 (4x8 micro). Dh=128 resident.
// Dynamic smem: Qs[128][68] + Ks[128][68] + Vs[64][132] + Ps[64][68]
#define QS_STR 68
#define VS_STR 132
#define ATTN_SMEM_FLOATS (128 * QS_STR * 2 + 64 * VS_STR + 64 * QS_STR)
#define ATTN_SMEM_BYTES  (ATTN_SMEM_FLOATS * 4)

__global__ __launch_bounds__(256, 1)
void attn_kernel(const float* __restrict__ Q, const float* __restrict__ K,
                 const float* __restrict__ V, float* __restrict__ O)
{
    extern __shared__ float sm[];
    float* Qs = sm;                        // [d][r]   128 x 68
    float* Ks = Qs + 128 * QS_STR;         // [d][j]   128 x 68
    float* Vs = Ks + 128 * QS_STR;         // [j][c]    64 x 132
    float* Ps = Vs + 64  * VS_STR;         // [r][j]    64 x 68

    const int tid = threadIdx.x;
    const int tx = tid & 15;
    const int ty = tid >> 4;
    const int bh = blockIdx.y;
    const int q0 = blockIdx.x * 64;
    const float scale = 0.08838834764831845f;   // 1/sqrt(128)

    // ---- load Q tile transposed (scale folded in) ----
    const float* Qg = Q + ((size_t)bh * T_SZ + q0) * DH_SZ;
#pragma unroll
    for (int i = 0; i < 8; i++) {
        int lin = tid + i * 256;
        int r   = lin >> 5;                 // 0..63
        int d4  = (lin & 31) << 2;          // 0..124
        float4 w = *reinterpret_cast<const float4*>(Qg + (size_t)r * DH_SZ + d4);
        Qs[(d4 + 0) * QS_STR + r] = w.x * scale;
        Qs[(d4 + 1) * QS_STR + r] = w.y * scale;
        Qs[(d4 + 2) * QS_STR + r] = w.z * scale;
        Qs[(d4 + 3) * QS_STR + r] = w.w * scale;
    }

    float o[4][8];
#pragma unroll
    for (int r = 0; r < 4; r++)
#pragma unroll
        for (int c = 0; c < 8; c++) o[r][c] = 0.0f;
    float mr[4], lr[4];
#pragma unroll
    for (int r = 0; r < 4; r++) { mr[r] = -INFINITY; lr[r] = 0.0f; }

    for (int kt = 0; kt < T_SZ / 64; kt++) {
        const float* Kg = K + ((size_t)bh * T_SZ + kt * 64) * DH_SZ;
        const float* Vg = V + ((size_t)bh * T_SZ + kt * 64) * DH_SZ;

        __syncthreads();   // previous iteration's Ks/Vs/Ps reads complete
        // ---- load K (transposed) and V (row-major) tiles ----
#pragma unroll
        for (int i = 0; i < 8; i++) {
            int lin = tid + i * 256;
            int j   = lin >> 5;
            int d4  = (lin & 31) << 2;
            float4 w = *reinterpret_cast<const float4*>(Kg + (size_t)j * DH_SZ + d4);
            Ks[(d4 + 0) * QS_STR + j] = w.x;
            Ks[(d4 + 1) * QS_STR + j] = w.y;
            Ks[(d4 + 2) * QS_STR + j] = w.z;
            Ks[(d4 + 3) * QS_STR + j] = w.w;
            float4 u = *reinterpret_cast<const float4*>(Vg + (size_t)j * DH_SZ + d4);
            *reinterpret_cast<float4*>(&Vs[j * VS_STR + d4]) = u;
        }
        __syncthreads();

        // ---- S = Q * K^T  (4x4 micro-tile) ----
        float s[4][4];
#pragma unroll
        for (int r = 0; r < 4; r++)
#pragma unroll
            for (int c = 0; c < 4; c++) s[r][c] = 0.0f;

#pragma unroll 4
        for (int d = 0; d < DH_SZ; d++) {
            float4 a = *reinterpret_cast<const float4*>(&Qs[d * QS_STR + ty * 4]);
            float4 b = *reinterpret_cast<const float4*>(&Ks[d * QS_STR + tx * 4]);
            float av[4] = {a.x, a.y, a.z, a.w};
            float bv[4] = {b.x, b.y, b.z, b.w};
#pragma unroll
            for (int r = 0; r < 4; r++)
#pragma unroll
                for (int c = 0; c < 4; c++)
                    s[r][c] += av[r] * bv[c];
        }

        // ---- online softmax (row reductions across 16 tx lanes) ----
#pragma unroll
        for (int r = 0; r < 4; r++) {
            float mx = fmaxf(fmaxf(s[r][0], s[r][1]), fmaxf(s[r][2], s[r][3]));
#pragma unroll
            for (int off = 1; off < 16; off <<= 1)
                mx = fmaxf(mx, __shfl_xor_sync(0xffffffffu, mx, off));
            float mnew  = fmaxf(mr[r], mx);
            float alpha = __expf(mr[r] - mnew);
            mr[r] = mnew;
            float rs = 0.0f;
#pragma unroll
            for (int c = 0; c < 4; c++) { s[r][c] = __expf(s[r][c] - mnew); rs += s[r][c]; }
#pragma unroll
            for (int off = 1; off < 16; off <<= 1)
                rs += __shfl_xor_sync(0xffffffffu, rs, off);
            lr[r] = lr[r] * alpha + rs;
#pragma unroll
            for (int c = 0; c < 8; c++) o[r][c] *= alpha;
            *reinterpret_cast<float4*>(&Ps[(ty * 4 + r) * QS_STR + tx * 4]) =
                make_float4(s[r][0], s[r][1], s[r][2], s[r][3]);
        }
        __syncthreads();

        // ---- O += P * V  (4x8 micro-tile) ----
#pragma unroll 2
        for (int j = 0; j < 64; j++) {
            float p0 = Ps[(ty * 4 + 0) * QS_STR + j];
            float p1 = Ps[(ty * 4 + 1) * QS_STR + j];
            float p2 = Ps[(ty * 4 + 2) * QS_STR + j];
            float p3 = Ps[(ty * 4 + 3) * QS_STR + j];
            float4 v0 = *reinterpret_cast<const float4*>(&Vs[j * VS_STR + tx * 8]);
            float4 v1 = *reinterpret_cast<const float4*>(&Vs[j * VS_STR + tx * 8 + 4]);
            float vv[8] = {v0.x, v0.y, v0.z, v0.w, v1.x, v1.y, v1.z, v1.w};
#pragma unroll
            for (int c = 0; c < 8; c++) {
                o[0][c] += p0 * vv[c];
                o[1][c] += p1 * vv[c];
                o[2][c] += p2 * vv[c];
                o[3][c] += p3 * vv[c];
            }
        }
    }

    // ---- epilogue: normalize, write ctx[b, t, h*128 + c] ----
    const int b_ = bh >> 4;
    const int h  = bh & 15;
#pragma unroll
    for (int r = 0; r < 4; r++) {
        float inv = 1.0f / lr[r];
        int t = q0 + ty * 4 + r;
        float* dst = O + ((size_t)(b_ * T_SZ + t)) * D_SZ + h * DH_SZ + tx * 8;
        *reinterpret_cast<float4*>(dst)     = make_float4(o[r][0] * inv, o[r][1] * inv,
                                                          o[r][2] * inv, o[r][3] * inv);
        *reinterpret_cast<float4*>(dst + 4) = make_float4(o[r][4] * inv, o[r][5] * inv,
                                                          o[r][6] * inv, o[r][7] * inv);
    }
}

// ================================ launch =====================================
extern "C" void kernel_launch(void* const* d_in, const int* in_sizes, int n_in,
                              void* d_out, int out_size)
{
    (void)in_sizes; (void)n_in; (void)out_size;
    const float* x  = (const float*)d_in[0];
    const float* Wq = (const float*)d_in[1];
    const float* bq = (const float*)d_in[2];
    const float* Wk = (const float*)d_in[3];
    const float* bk = (const float*)d_in[4];
    const float* Wv = (const float*)d_in[5];
    const float* bv = (const float*)d_in[6];
    const float* Wo = (const float*)d_in[7];
    const float* bo = (const float*)d_in[8];
    float* out = (float*)d_out;

    float *q, *k, *v, *ctx;
    cudaGetSymbolAddress((void**)&q,   g_q);
    cudaGetSymbolAddress((void**)&k,   g_k);
    cudaGetSymbolAddress((void**)&v,   g_v);
    cudaGetSymbolAddress((void**)&ctx, g_ctx);

    cudaFuncSetAttribute(attn_kernel,
                         cudaFuncAttributeMaxDynamicSharedMemorySize,
                         ATTN_SMEM_BYTES);

    dim3 ggrid(D_SZ / BN, M_ROWS / BM);   // 32 x 64

    gemm_bias<<<ggrid, 256>>>(x, Wq, bq, q, 1);
    gemm_bias<<<ggrid, 256>>>(x, Wk, bk, k, 1);
    gemm_bias<<<ggrid, 256>>>(x, Wv, bv, v, 1);

    dim3 agrid(T_SZ / 64, B_SZ * H_SZ);   // 32 x 64
    attn_kernel<<<agrid, 256, ATTN_SMEM_BYTES>>>(q, k, v, ctx);

    gemm_bias<<<ggrid, 256>>>(ctx, Wo, bo, out, 0);
}

// round 12
// speedup vs baseline: 1.6820x; 1.6820x over previous
#include <cuda_runtime.h>
#include <cuda_bf16.h>
#include <stdint.h>
#include <math.h>

// Problem constants
#define B_SZ    4
#define T_SZ    2048
#define D_SZ    2048
#define H_SZ    16
#define DH_SZ   128
#define M_ROWS  (B_SZ * T_SZ)        // 8192

// ---------------- scratch (no-alloc rule: __device__ globals) ----------------
__device__ float g_q[(size_t)B_SZ * H_SZ * T_SZ * DH_SZ];   // [B,H,T,Dh]
__device__ float g_k[(size_t)B_SZ * H_SZ * T_SZ * DH_SZ];
__device__ float g_v[(size_t)B_SZ * H_SZ * T_SZ * DH_SZ];
__device__ float g_ctx[(size_t)B_SZ * T_SZ * D_SZ];         // [B,T,D]
// bf16 split buffers (activation buffers reused for x and ctx; W buffers reused per proj)
__device__ __nv_bfloat16 g_ahi[(size_t)M_ROWS * D_SZ];
__device__ __nv_bfloat16 g_alo[(size_t)M_ROWS * D_SZ];
__device__ __nv_bfloat16 g_whi[(size_t)D_SZ * D_SZ];
__device__ __nv_bfloat16 g_wlo[(size_t)D_SZ * D_SZ];

// ===================== split fp32 -> (bf16 hi, bf16 lo) ======================
__global__ __launch_bounds__(256)
void split_bf16(const float* __restrict__ src,
                __nv_bfloat16* __restrict__ hi,
                __nv_bfloat16* __restrict__ lo, int n4)
{
    int i = blockIdx.x * blockDim.x + threadIdx.x;
    if (i >= n4) return;
    float4 v = reinterpret_cast<const float4*>(src)[i];
    __nv_bfloat16 hx = __float2bfloat16(v.x);
    __nv_bfloat16 hy = __float2bfloat16(v.y);
    __nv_bfloat16 hz = __float2bfloat16(v.z);
    __nv_bfloat16 hw = __float2bfloat16(v.w);
    __nv_bfloat162 h01; h01.x = hx; h01.y = hy;
    __nv_bfloat162 h23; h23.x = hz; h23.y = hw;
    __nv_bfloat162 l01;
    l01.x = __float2bfloat16(v.x - __bfloat162float(hx));
    l01.y = __float2bfloat16(v.y - __bfloat162float(hy));
    __nv_bfloat162 l23;
    l23.x = __float2bfloat16(v.z - __bfloat162float(hz));
    l23.y = __float2bfloat16(v.w - __bfloat162float(hw));
    reinterpret_cast<__nv_bfloat162*>(hi)[i * 2 + 0] = h01;
    reinterpret_cast<__nv_bfloat162*>(hi)[i * 2 + 1] = h23;
    reinterpret_cast<__nv_bfloat162*>(lo)[i * 2 + 0] = l01;
    reinterpret_cast<__nv_bfloat162*>(lo)[i * 2 + 1] = l23;
}

// ============== bf16x3 tensor-core GEMM: C = A * W^T + bias ==================
// C[m,n] = sum_k A[m,k]*W[n,k], A,W given as (hi,lo) bf16 splits.
// Block 128x128x32, 256 threads, 8 warps as 2(m) x 4(n), warp tile 64x32.
// mma.sync.aligned.m16n8k16.row.col.f32.bf16.bf16.f32, 3 MMAs per atom
// (hi*hi + hi*lo + lo*hi); residual lo*lo ~ 2^-18, negligible.
#define MMA_BF16(c, a0,a1,a2,a3, b0,b1)                                   \
    asm volatile(                                                         \
        "mma.sync.aligned.m16n8k16.row.col.f32.bf16.bf16.f32 "            \
        "{%0,%1,%2,%3}, {%4,%5,%6,%7}, {%8,%9}, {%0,%1,%2,%3};"           \
        : "+f"(c[0]), "+f"(c[1]), "+f"(c[2]), "+f"(c[3])                  \
        : "r"(a0), "r"(a1), "r"(a2), "r"(a3), "r"(b0), "r"(b1))

#define GBM 128
#define GBN 128
#define GBK 32
#define SA_STR 40   // padded smem row (bf16): conflict-free fragment reads

__global__ __launch_bounds__(256)
void gemm_mma(const __nv_bfloat16* __restrict__ Ahi, const __nv_bfloat16* __restrict__ Alo,
              const __nv_bfloat16* __restrict__ Whi, const __nv_bfloat16* __restrict__ Wlo,
              const float* __restrict__ bias, float* __restrict__ C, int headMajor)
{
    __shared__ __nv_bfloat16 sAh[GBM][SA_STR];
    __shared__ __nv_bfloat16 sAl[GBM][SA_STR];
    __shared__ __nv_bfloat16 sWh[GBN][SA_STR];
    __shared__ __nv_bfloat16 sWl[GBN][SA_STR];

    const int tid  = threadIdx.x;
    const int wid  = tid >> 5;
    const int lane = tid & 31;
    const int wm   = (wid >> 2) * 64;      // warp m offset: 0 or 64
    const int wn   = (wid & 3) * 32;       // warp n offset: 0,32,64,96
    const int gr   = lane >> 2;            // fragment group row 0..7
    const int qp   = (lane & 3) * 2;       // fragment k/n pair base

    const int m0 = blockIdx.y * GBM;
    const int n0 = blockIdx.x * GBN;

    // ---- gmem tile-load coordinates: 128x32 bf16 = 512 uint4, 2/thread ----
    const int lr = tid >> 2;               // rows lr and lr+64
    const int lc = (tid & 3) * 8;          // bf16 column
    const size_t gA0 = (size_t)(m0 + lr)      * D_SZ + lc;
    const size_t gA1 = (size_t)(m0 + lr + 64) * D_SZ + lc;
    const size_t gW0 = (size_t)(n0 + lr)      * D_SZ + lc;
    const size_t gW1 = (size_t)(n0 + lr + 64) * D_SZ + lc;

    float acc[4][4][4];
#pragma unroll
    for (int i = 0; i < 4; i++)
#pragma unroll
        for (int j = 0; j < 4; j++)
#pragma unroll
            for (int r = 0; r < 4; r++) acc[i][j][r] = 0.0f;

    // ---- prologue prefetch (k0 = 0) ----
    uint4 pAh0 = *reinterpret_cast<const uint4*>(Ahi + gA0);
    uint4 pAh1 = *reinterpret_cast<const uint4*>(Ahi + gA1);
    uint4 pAl0 = *reinterpret_cast<const uint4*>(Alo + gA0);
    uint4 pAl1 = *reinterpret_cast<const uint4*>(Alo + gA1);
    uint4 pWh0 = *reinterpret_cast<const uint4*>(Whi + gW0);
    uint4 pWh1 = *reinterpret_cast<const uint4*>(Whi + gW1);
    uint4 pWl0 = *reinterpret_cast<const uint4*>(Wlo + gW0);
    uint4 pWl1 = *reinterpret_cast<const uint4*>(Wlo + gW1);

    for (int k0 = 0; k0 < D_SZ; k0 += GBK) {
        // ---- commit prefetched tiles to smem ----
        *reinterpret_cast<uint4*>(&sAh[lr][lc])      = pAh0;
        *reinterpret_cast<uint4*>(&sAh[lr + 64][lc]) = pAh1;
        *reinterpret_cast<uint4*>(&sAl[lr][lc])      = pAl0;
        *reinterpret_cast<uint4*>(&sAl[lr + 64][lc]) = pAl1;
        *reinterpret_cast<uint4*>(&sWh[lr][lc])      = pWh0;
        *reinterpret_cast<uint4*>(&sWh[lr + 64][lc]) = pWh1;
        *reinterpret_cast<uint4*>(&sWl[lr][lc])      = pWl0;
        *reinterpret_cast<uint4*>(&sWl[lr + 64][lc]) = pWl1;
        __syncthreads();

        // ---- prefetch next k-tile (overlaps MMA mainloop) ----
        const int kn = k0 + GBK;
        if (kn < D_SZ) {
            pAh0 = *reinterpret_cast<const uint4*>(Ahi + gA0 + kn);
            pAh1 = *reinterpret_cast<const uint4*>(Ahi + gA1 + kn);
            pAl0 = *reinterpret_cast<const uint4*>(Alo + gA0 + kn);
            pAl1 = *reinterpret_cast<const uint4*>(Alo + gA1 + kn);
            pWh0 = *reinterpret_cast<const uint4*>(Whi + gW0 + kn);
            pWh1 = *reinterpret_cast<const uint4*>(Whi + gW1 + kn);
            pWl0 = *reinterpret_cast<const uint4*>(Wlo + gW0 + kn);
            pWl1 = *reinterpret_cast<const uint4*>(Wlo + gW1 + kn);
        }

        // ---- MMA mainloop: 2 x k16 steps ----
#pragma unroll
        for (int kk = 0; kk < 2; kk++) {
            const int kb = kk * 16;
            uint32_t ah[4][4], al[4][4], bh[4][2], bl[4][2];
#pragma unroll
            for (int i = 0; i < 4; i++) {
                const int mr = wm + i * 16 + gr;
                ah[i][0] = *reinterpret_cast<const uint32_t*>(&sAh[mr][kb + qp]);
                ah[i][1] = *reinterpret_cast<const uint32_t*>(&sAh[mr + 8][kb + qp]);
                ah[i][2] = *reinterpret_cast<const uint32_t*>(&sAh[mr][kb + qp + 8]);
                ah[i][3] = *reinterpret_cast<const uint32_t*>(&sAh[mr + 8][kb + qp + 8]);
                al[i][0] = *reinterpret_cast<const uint32_t*>(&sAl[mr][kb + qp]);
                al[i][1] = *reinterpret_cast<const uint32_t*>(&sAl[mr + 8][kb + qp]);
                al[i][2] = *reinterpret_cast<const uint32_t*>(&sAl[mr][kb + qp + 8]);
                al[i][3] = *reinterpret_cast<const uint32_t*>(&sAl[mr + 8][kb + qp + 8]);
            }
#pragma unroll
            for (int j = 0; j < 4; j++) {
                const int nr = wn + j * 8 + gr;
                bh[j][0] = *reinterpret_cast<const uint32_t*>(&sWh[nr][kb + qp]);
                bh[j][1] = *reinterpret_cast<const uint32_t*>(&sWh[nr][kb + qp + 8]);
                bl[j][0] = *reinterpret_cast<const uint32_t*>(&sWl[nr][kb + qp]);
                bl[j][1] = *reinterpret_cast<const uint32_t*>(&sWl[nr][kb + qp + 8]);
            }
#pragma unroll
            for (int i = 0; i < 4; i++)
#pragma unroll
                for (int j = 0; j < 4; j++) {
                    MMA_BF16(acc[i][j], ah[i][0], ah[i][1], ah[i][2], ah[i][3],
                             bh[j][0], bh[j][1]);
                    MMA_BF16(acc[i][j], ah[i][0], ah[i][1], ah[i][2], ah[i][3],
                             bl[j][0], bl[j][1]);
                    MMA_BF16(acc[i][j], al[i][0], al[i][1], al[i][2], al[i][3],
                             bh[j][0], bh[j][1]);
                }
        }
        __syncthreads();
    }

    // ---- epilogue: +bias, write (headMajor or rowMajor) ----
#pragma unroll
    for (int j = 0; j < 4; j++) {
        const int n = n0 + wn + j * 8 + qp;
        const float2 bb = *reinterpret_cast<const float2*>(&bias[n]);
#pragma unroll
        for (int i = 0; i < 4; i++) {
            const int m = m0 + wm + i * 16 + gr;
            float2 o0, o1;
            o0.x = acc[i][j][0] + bb.x;  o0.y = acc[i][j][1] + bb.y;
            o1.x = acc[i][j][2] + bb.x;  o1.y = acc[i][j][3] + bb.y;
            if (headMajor) {
                const int h  = n >> 7;
                const int dh = n & 127;
                const int b_ = m >> 11;
                const int t  = m & 2047;
                float* base = C + ((((size_t)b_ * H_SZ + h) * T_SZ + t) * DH_SZ + dh);
                *reinterpret_cast<float2*>(base) = o0;
                *reinterpret_cast<float2*>(base + (size_t)8 * DH_SZ) = o1;  // m+8 row
            } else {
                *reinterpret_cast<float2*>(C + (size_t)m * D_SZ + n) = o0;
                *reinterpret_cast<float2*>(C + (size_t)(m + 8) * D_SZ + n) = o1;
            }
        }
    }
}

// ===================== Flash attention (fp32, online softmax) ================
// K/V tiles are prefetched gmem->reg during the previous iteration's compute
// phase (1 CTA/SM: barrier stalls hit all warps, so latency must be hidden
// inside the instruction stream, not by other warps).
#define QS_STR 68
#define VS_STR 132
#define ATTN_SMEM_FLOATS (128 * QS_STR * 2 + 64 * VS_STR + 64 * QS_STR)
#define ATTN_SMEM_BYTES  (ATTN_SMEM_FLOATS * 4)

__global__ __launch_bounds__(256, 1)
void attn_kernel(const float* __restrict__ Q, const float* __restrict__ K,
                 const float* __restrict__ V, float* __restrict__ O)
{
    extern __shared__ float sm[];
    float* Qs = sm;                        // [d][r]   128 x 68
    float* Ks = Qs + 128 * QS_STR;         // [d][j]   128 x 68
    float* Vs = Ks + 128 * QS_STR;         // [j][c]    64 x 132
    float* Ps = Vs + 64  * VS_STR;         // [r][j]    64 x 68

    const int tid = threadIdx.x;
    const int tx = tid & 15;
    const int ty = tid >> 4;
    const int bh = blockIdx.y;
    const int q0 = blockIdx.x * 64;
    const float scale = 0.08838834764831845f;   // 1/sqrt(128)

    // per-thread K/V tile coordinates: chunk i covers row j = pj + i*8
    const int pj  = tid >> 5;              // 0..7
    const int pd4 = (tid & 31) << 2;       // d column base 0..124

    const float* Qg = Q + ((size_t)bh * T_SZ + q0) * DH_SZ;
#pragma unroll
    for (int i = 0; i < 8; i++) {
        int r = pj + i * 8;
        float4 w = *reinterpret_cast<const float4*>(Qg + (size_t)r * DH_SZ + pd4);
        Qs[(pd4 + 0) * QS_STR + r] = w.x * scale;
        Qs[(pd4 + 1) * QS_STR + r] = w.y * scale;
        Qs[(pd4 + 2) * QS_STR + r] = w.z * scale;
        Qs[(pd4 + 3) * QS_STR + r] = w.w * scale;
    }

    // ---- prologue: prefetch kt=0 K/V into registers ----
    const float* KgBase = K + (size_t)bh * T_SZ * DH_SZ;
    const float* VgBase = V + (size_t)bh * T_SZ * DH_SZ;
    float4 kReg[8], vReg[8];
#pragma unroll
    for (int i = 0; i < 8; i++) {
        int j = pj + i * 8;
        kReg[i] = *reinterpret_cast<const float4*>(KgBase + (size_t)j * DH_SZ + pd4);
        vReg[i] = *reinterpret_cast<const float4*>(VgBase + (size_t)j * DH_SZ + pd4);
    }

    float o[4][8];
#pragma unroll
    for (int r = 0; r < 4; r++)
#pragma unroll
        for (int c = 0; c < 8; c++) o[r][c] = 0.0f;
    float mr[4], lr[4];
#pragma unroll
    for (int r = 0; r < 4; r++) { mr[r] = -INFINITY; lr[r] = 0.0f; }

    for (int kt = 0; kt < T_SZ / 64; kt++) {
        __syncthreads();   // previous iteration's Ks/Vs/Ps reads complete
        // ---- commit prefetched K (transposed) / V (row-major) to smem ----
#pragma unroll
        for (int i = 0; i < 8; i++) {
            int j = pj + i * 8;
            Ks[(pd4 + 0) * QS_STR + j] = kReg[i].x;
            Ks[(pd4 + 1) * QS_STR + j] = kReg[i].y;
            Ks[(pd4 + 2) * QS_STR + j] = kReg[i].z;
            Ks[(pd4 + 3) * QS_STR + j] = kReg[i].w;
            *reinterpret_cast<float4*>(&Vs[j * VS_STR + pd4]) = vReg[i];
        }
        __syncthreads();

        // ---- prefetch next K/V tile (overlaps S/softmax/PV below) ----
        if (kt + 1 < T_SZ / 64) {
            const float* Kg = KgBase + (size_t)(kt + 1) * 64 * DH_SZ;
            const float* Vg = VgBase + (size_t)(kt + 1) * 64 * DH_SZ;
#pragma unroll
            for (int i = 0; i < 8; i++) {
                int j = pj + i * 8;
                kReg[i] = *reinterpret_cast<const float4*>(Kg + (size_t)j * DH_SZ + pd4);
                vReg[i] = *reinterpret_cast<const float4*>(Vg + (size_t)j * DH_SZ + pd4);
            }
        }

        // ---- S = Q * K^T  (4x4 micro-tile) ----
        float s[4][4];
#pragma unroll
        for (int r = 0; r < 4; r++)
#pragma unroll
            for (int c = 0; c < 4; c++) s[r][c] = 0.0f;

#pragma unroll 4
        for (int d = 0; d < DH_SZ; d++) {
            float4 a = *reinterpret_cast<const float4*>(&Qs[d * QS_STR + ty * 4]);
            float4 b = *reinterpret_cast<const float4*>(&Ks[d * QS_STR + tx * 4]);
            float av[4] = {a.x, a.y, a.z, a.w};
            float bv[4] = {b.x, b.y, b.z, b.w};
#pragma unroll
            for (int r = 0; r < 4; r++)
#pragma unroll
                for (int c = 0; c < 4; c++)
                    s[r][c] += av[r] * bv[c];
        }

        // ---- online softmax (row reductions across 16 tx lanes) ----
#pragma unroll
        for (int r = 0; r < 4; r++) {
            float mx = fmaxf(fmaxf(s[r][0], s[r][1]), fmaxf(s[r][2], s[r][3]));
#pragma unroll
            for (int off = 1; off < 16; off <<= 1)
                mx = fmaxf(mx, __shfl_xor_sync(0xffffffffu, mx, off));
            float mnew  = fmaxf(mr[r], mx);
            float alpha = __expf(mr[r] - mnew);
            mr[r] = mnew;
            float rs = 0.0f;
#pragma unroll
            for (int c = 0; c < 4; c++) { s[r][c] = __expf(s[r][c] - mnew); rs += s[r][c]; }
#pragma unroll
            for (int off = 1; off < 16; off <<= 1)
                rs += __shfl_xor_sync(0xffffffffu, rs, off);
            lr[r] = lr[r] * alpha + rs;
#pragma unroll
            for (int c = 0; c < 8; c++) o[r][c] *= alpha;
            *reinterpret_cast<float4*>(&Ps[(ty * 4 + r) * QS_STR + tx * 4]) =
                make_float4(s[r][0], s[r][1], s[r][2], s[r][3]);
        }
        __syncthreads();

        // ---- O += P * V  (4x8 micro-tile) ----
#pragma unroll 2
        for (int j = 0; j < 64; j++) {
            float p0 = Ps[(ty * 4 + 0) * QS_STR + j];
            float p1 = Ps[(ty * 4 + 1) * QS_STR + j];
            float p2 = Ps[(ty * 4 + 2) * QS_STR + j];
            float p3 = Ps[(ty * 4 + 3) * QS_STR + j];
            float4 v0 = *reinterpret_cast<const float4*>(&Vs[j * VS_STR + tx * 8]);
            float4 v1 = *reinterpret_cast<const float4*>(&Vs[j * VS_STR + tx * 8 + 4]);
            float vv[8] = {v0.x, v0.y, v0.z, v0.w, v1.x, v1.y, v1.z, v1.w};
#pragma unroll
            for (int c = 0; c < 8; c++) {
                o[0][c] += p0 * vv[c];
                o[1][c] += p1 * vv[c];
                o[2][c] += p2 * vv[c];
                o[3][c] += p3 * vv[c];
            }
        }
    }

    const int b_ = bh >> 4;
    const int h  = bh & 15;
#pragma unroll
    for (int r = 0; r < 4; r++) {
        float inv = 1.0f / lr[r];
        int t = q0 + ty * 4 + r;
        float* dst = O + ((size_t)(b_ * T_SZ + t)) * D_SZ + h * DH_SZ + tx * 8;
        *reinterpret_cast<float4*>(dst)     = make_float4(o[r][0] * inv, o[r][1] * inv,
                                                          o[r][2] * inv, o[r][3] * inv);
        *reinterpret_cast<float4*>(dst + 4) = make_float4(o[r][4] * inv, o[r][5] * inv,
                                                          o[r][6] * inv, o[r][7] * inv);
    }
}

// ================================ launch =====================================
extern "C" void kernel_launch(void* const* d_in, const int* in_sizes, int n_in,
                              void* d_out, int out_size)
{
    (void)in_sizes; (void)n_in; (void)out_size;
    const float* x  = (const float*)d_in[0];
    const float* Wq = (const float*)d_in[1];
    const float* bq = (const float*)d_in[2];
    const float* Wk = (const float*)d_in[3];
    const float* bk = (const float*)d_in[4];
    const float* Wv = (const float*)d_in[5];
    const float* bv = (const float*)d_in[6];
    const float* Wo = (const float*)d_in[7];
    const float* bo = (const float*)d_in[8];
    float* out = (float*)d_out;

    float *q, *k, *v, *ctx;
    __nv_bfloat16 *ahi, *alo, *whi, *wlo;
    cudaGetSymbolAddress((void**)&q,   g_q);
    cudaGetSymbolAddress((void**)&k,   g_k);
    cudaGetSymbolAddress((void**)&v,   g_v);
    cudaGetSymbolAddress((void**)&ctx, g_ctx);
    cudaGetSymbolAddress((void**)&ahi, g_ahi);
    cudaGetSymbolAddress((void**)&alo, g_alo);
    cudaGetSymbolAddress((void**)&whi, g_whi);
    cudaGetSymbolAddress((void**)&wlo, g_wlo);

    cudaFuncSetAttribute(attn_kernel,
                         cudaFuncAttributeMaxDynamicSharedMemorySize,
                         ATTN_SMEM_BYTES);

    const int nx4 = M_ROWS * D_SZ / 4;   // x / ctx elements in float4
    const int nw4 = D_SZ * D_SZ / 4;
    dim3 ggrid(D_SZ / GBN, M_ROWS / GBM);   // 16 x 64

    // x -> bf16 splits (used by q,k,v projections)
    split_bf16<<<(nx4 + 255) / 256, 256>>>(x, ahi, alo, nx4);

    split_bf16<<<(nw4 + 255) / 256, 256>>>(Wq, whi, wlo, nw4);
    gemm_mma<<<ggrid, 256>>>(ahi, alo, whi, wlo, bq, q, 1);
    split_bf16<<<(nw4 + 255) / 256, 256>>>(Wk, whi, wlo, nw4);
    gemm_mma<<<ggrid, 256>>>(ahi, alo, whi, wlo, bk, k, 1);
    split_bf16<<<(nw4 + 255) / 256, 256>>>(Wv, whi, wlo, nw4);
    gemm_mma<<<ggrid, 256>>>(ahi, alo, whi, wlo, bv, v, 1);

    dim3 agrid(T_SZ / 64, B_SZ * H_SZ);   // 32 x 64
    attn_kernel<<<agrid, 256, ATTN_SMEM_BYTES>>>(q, k, v, ctx);

    // ctx -> bf16 splits (reuse activation buffers), then output projection
    split_bf16<<<(nx4 + 255) / 256, 256>>>(ctx, ahi, alo, nx4);
    split_bf16<<<(nw4 + 255) / 256, 256>>>(Wo, whi, wlo, nw4);
    gemm_mma<<<ggrid, 256>>>(ahi, alo, whi, wlo, bo, out, 0);
}

// round 17
// speedup vs baseline: 3.4485x; 2.0502x over previous
#include <cuda_runtime.h>
#include <cuda_bf16.h>
#include <stdint.h>
#include <math.h>

// Problem constants
#define B_SZ    4
#define T_SZ    2048
#define D_SZ    2048
#define H_SZ    16
#define DH_SZ   128
#define M_ROWS  (B_SZ * T_SZ)        // 8192

// ---------------- scratch (no-alloc rule: __device__ globals) ----------------
__device__ float g_ctx[(size_t)M_ROWS * D_SZ];              // [B,T,D]
__device__ __nv_bfloat16 g_ahi[(size_t)M_ROWS * D_SZ];      // activation splits
__device__ __nv_bfloat16 g_alo[(size_t)M_ROWS * D_SZ];
__device__ __nv_bfloat16 g_whi[(size_t)D_SZ * D_SZ];        // weight splits
__device__ __nv_bfloat16 g_wlo[(size_t)D_SZ * D_SZ];
// pre-split attention operands (written by gemm epilogue)
__device__ __nv_bfloat16 g_qhi[(size_t)M_ROWS * D_SZ];      // [B,H,T,Dh], scale folded
__device__ __nv_bfloat16 g_qlo[(size_t)M_ROWS * D_SZ];
__device__ __nv_bfloat16 g_khi[(size_t)M_ROWS * D_SZ];      // [B,H,T,Dh]
__device__ __nv_bfloat16 g_klo[(size_t)M_ROWS * D_SZ];
__device__ __nv_bfloat16 g_vthi[(size_t)M_ROWS * D_SZ];     // [B,H,Dh,T] (transposed)
__device__ __nv_bfloat16 g_vtlo[(size_t)M_ROWS * D_SZ];

// ===================== split fp32 -> (bf16 hi, bf16 lo) ======================
__global__ __launch_bounds__(256)
void split_bf16(const float* __restrict__ src,
                __nv_bfloat16* __restrict__ hi,
                __nv_bfloat16* __restrict__ lo, int n4)
{
    int i = blockIdx.x * blockDim.x + threadIdx.x;
    if (i >= n4) return;
    float4 v = reinterpret_cast<const float4*>(src)[i];
    __nv_bfloat16 hx = __float2bfloat16(v.x);
    __nv_bfloat16 hy = __float2bfloat16(v.y);
    __nv_bfloat16 hz = __float2bfloat16(v.z);
    __nv_bfloat16 hw = __float2bfloat16(v.w);
    __nv_bfloat162 h01; h01.x = hx; h01.y = hy;
    __nv_bfloat162 h23; h23.x = hz; h23.y = hw;
    __nv_bfloat162 l01;
    l01.x = __float2bfloat16(v.x - __bfloat162float(hx));
    l01.y = __float2bfloat16(v.y - __bfloat162float(hy));
    __nv_bfloat162 l23;
    l23.x = __float2bfloat16(v.z - __bfloat162float(hz));
    l23.y = __float2bfloat16(v.w - __bfloat162float(hw));
    reinterpret_cast<__nv_bfloat162*>(hi)[i * 2 + 0] = h01;
    reinterpret_cast<__nv_bfloat162*>(hi)[i * 2 + 1] = h23;
    reinterpret_cast<__nv_bfloat162*>(lo)[i * 2 + 0] = l01;
    reinterpret_cast<__nv_bfloat162*>(lo)[i * 2 + 1] = l23;
}

// ============== bf16x3 tensor-core GEMM: C = A * W^T + bias ==================
#define MMA_BF16(c, a0,a1,a2,a3, b0,b1)                                   \
    asm volatile(                                                         \
        "mma.sync.aligned.m16n8k16.row.col.f32.bf16.bf16.f32 "            \
        "{%0,%1,%2,%3}, {%4,%5,%6,%7}, {%8,%9}, {%0,%1,%2,%3};"           \
        : "+f"(c[0]), "+f"(c[1]), "+f"(c[2]), "+f"(c[3])                  \
        : "r"(a0), "r"(a1), "r"(a2), "r"(a3), "r"(b0), "r"(b1))

#define GBM 128
#define GBN 128
#define GBK 32
#define SA_STR 40

// mode 0: fp32 row-major to Cf.  mode 1: bf16 split head-major [B,H,T,Dh] with scale.
// mode 2: bf16 split head-major TRANSPOSED [B,H,Dh,T].
__global__ __launch_bounds__(256)
void gemm_mma(const __nv_bfloat16* __restrict__ Ahi, const __nv_bfloat16* __restrict__ Alo,
              const __nv_bfloat16* __restrict__ Whi, const __nv_bfloat16* __restrict__ Wlo,
              const float* __restrict__ bias, float* __restrict__ Cf,
              __nv_bfloat16* __restrict__ Chi, __nv_bfloat16* __restrict__ Clo,
              int mode, float scale)
{
    __shared__ __nv_bfloat16 sAh[GBM][SA_STR];
    __shared__ __nv_bfloat16 sAl[GBM][SA_STR];
    __shared__ __nv_bfloat16 sWh[GBN][SA_STR];
    __shared__ __nv_bfloat16 sWl[GBN][SA_STR];

    const int tid  = threadIdx.x;
    const int wid  = tid >> 5;
    const int lane = tid & 31;
    const int wm   = (wid >> 2) * 64;
    const int wn   = (wid & 3) * 32;
    const int gr   = lane >> 2;
    const int qp   = (lane & 3) * 2;

    const int m0 = blockIdx.y * GBM;
    const int n0 = blockIdx.x * GBN;

    const int lr = tid >> 2;
    const int lc = (tid & 3) * 8;
    const size_t gA0 = (size_t)(m0 + lr)      * D_SZ + lc;
    const size_t gA1 = (size_t)(m0 + lr + 64) * D_SZ + lc;
    const size_t gW0 = (size_t)(n0 + lr)      * D_SZ + lc;
    const size_t gW1 = (size_t)(n0 + lr + 64) * D_SZ + lc;

    float acc[4][4][4];
#pragma unroll
    for (int i = 0; i < 4; i++)
#pragma unroll
        for (int j = 0; j < 4; j++)
#pragma unroll
            for (int r = 0; r < 4; r++) acc[i][j][r] = 0.0f;

    uint4 pAh0 = *reinterpret_cast<const uint4*>(Ahi + gA0);
    uint4 pAh1 = *reinterpret_cast<const uint4*>(Ahi + gA1);
    uint4 pAl0 = *reinterpret_cast<const uint4*>(Alo + gA0);
    uint4 pAl1 = *reinterpret_cast<const uint4*>(Alo + gA1);
    uint4 pWh0 = *reinterpret_cast<const uint4*>(Whi + gW0);
    uint4 pWh1 = *reinterpret_cast<const uint4*>(Whi + gW1);
    uint4 pWl0 = *reinterpret_cast<const uint4*>(Wlo + gW0);
    uint4 pWl1 = *reinterpret_cast<const uint4*>(Wlo + gW1);

    for (int k0 = 0; k0 < D_SZ; k0 += GBK) {
        *reinterpret_cast<uint4*>(&sAh[lr][lc])      = pAh0;
        *reinterpret_cast<uint4*>(&sAh[lr + 64][lc]) = pAh1;
        *reinterpret_cast<uint4*>(&sAl[lr][lc])      = pAl0;
        *reinterpret_cast<uint4*>(&sAl[lr + 64][lc]) = pAl1;
        *reinterpret_cast<uint4*>(&sWh[lr][lc])      = pWh0;
        *reinterpret_cast<uint4*>(&sWh[lr + 64][lc]) = pWh1;
        *reinterpret_cast<uint4*>(&sWl[lr][lc])      = pWl0;
        *reinterpret_cast<uint4*>(&sWl[lr + 64][lc]) = pWl1;
        __syncthreads();

        const int kn = k0 + GBK;
        if (kn < D_SZ) {
            pAh0 = *reinterpret_cast<const uint4*>(Ahi + gA0 + kn);
            pAh1 = *reinterpret_cast<const uint4*>(Ahi + gA1 + kn);
            pAl0 = *reinterpret_cast<const uint4*>(Alo + gA0 + kn);
            pAl1 = *reinterpret_cast<const uint4*>(Alo + gA1 + kn);
            pWh0 = *reinterpret_cast<const uint4*>(Whi + gW0 + kn);
            pWh1 = *reinterpret_cast<const uint4*>(Whi + gW1 + kn);
            pWl0 = *reinterpret_cast<const uint4*>(Wlo + gW0 + kn);
            pWl1 = *reinterpret_cast<const uint4*>(Wlo + gW1 + kn);
        }

#pragma unroll
        for (int kk = 0; kk < 2; kk++) {
            const int kb = kk * 16;
            uint32_t ah[4][4], al[4][4], bh[4][2], bl[4][2];
#pragma unroll
            for (int i = 0; i < 4; i++) {
                const int mr = wm + i * 16 + gr;
                ah[i][0] = *reinterpret_cast<const uint32_t*>(&sAh[mr][kb + qp]);
                ah[i][1] = *reinterpret_cast<const uint32_t*>(&sAh[mr + 8][kb + qp]);
                ah[i][2] = *reinterpret_cast<const uint32_t*>(&sAh[mr][kb + qp + 8]);
                ah[i][3] = *reinterpret_cast<const uint32_t*>(&sAh[mr + 8][kb + qp + 8]);
                al[i][0] = *reinterpret_cast<const uint32_t*>(&sAl[mr][kb + qp]);
                al[i][1] = *reinterpret_cast<const uint32_t*>(&sAl[mr + 8][kb + qp]);
                al[i][2] = *reinterpret_cast<const uint32_t*>(&sAl[mr][kb + qp + 8]);
                al[i][3] = *reinterpret_cast<const uint32_t*>(&sAl[mr + 8][kb + qp + 8]);
            }
#pragma unroll
            for (int j = 0; j < 4; j++) {
                const int nr = wn + j * 8 + gr;
                bh[j][0] = *reinterpret_cast<const uint32_t*>(&sWh[nr][kb + qp]);
                bh[j][1] = *reinterpret_cast<const uint32_t*>(&sWh[nr][kb + qp + 8]);
                bl[j][0] = *reinterpret_cast<const uint32_t*>(&sWl[nr][kb + qp]);
                bl[j][1] = *reinterpret_cast<const uint32_t*>(&sWl[nr][kb + qp + 8]);
            }
#pragma unroll
            for (int i = 0; i < 4; i++)
#pragma unroll
                for (int j = 0; j < 4; j++) {
                    MMA_BF16(acc[i][j], ah[i][0], ah[i][1], ah[i][2], ah[i][3],
                             bh[j][0], bh[j][1]);
                    MMA_BF16(acc[i][j], ah[i][0], ah[i][1], ah[i][2], ah[i][3],
                             bl[j][0], bl[j][1]);
                    MMA_BF16(acc[i][j], al[i][0], al[i][1], al[i][2], al[i][3],
                             bh[j][0], bh[j][1]);
                }
        }
        __syncthreads();
    }

    // ---- epilogue ----
#pragma unroll
    for (int j = 0; j < 4; j++) {
        const int n = n0 + wn + j * 8 + qp;
        const float2 bb = *reinterpret_cast<const float2*>(&bias[n]);
#pragma unroll
        for (int i = 0; i < 4; i++) {
            const int m = m0 + wm + i * 16 + gr;
            float y00 = (acc[i][j][0] + bb.x) * scale;
            float y01 = (acc[i][j][1] + bb.y) * scale;
            float y10 = (acc[i][j][2] + bb.x) * scale;
            float y11 = (acc[i][j][3] + bb.y) * scale;
            if (mode == 0) {
                float2 o0; o0.x = y00; o0.y = y01;
                float2 o1; o1.x = y10; o1.y = y11;
                *reinterpret_cast<float2*>(Cf + (size_t)m * D_SZ + n) = o0;
                *reinterpret_cast<float2*>(Cf + (size_t)(m + 8) * D_SZ + n) = o1;
            } else {
                const int h  = n >> 7;
                const int dh = n & 127;
                const int b_ = m >> 11;
                const int t  = m & 2047;
                if (mode == 1) {
                    size_t base0 = (((size_t)(b_ * H_SZ + h) * T_SZ + t) * DH_SZ + dh);
                    size_t base1 = base0 + (size_t)8 * DH_SZ;
                    __nv_bfloat162 h0 = __floats2bfloat162_rn(y00, y01);
                    __nv_bfloat162 l0 = __floats2bfloat162_rn(y00 - __bfloat162float(h0.x),
                                                              y01 - __bfloat162float(h0.y));
                    __nv_bfloat162 h1 = __floats2bfloat162_rn(y10, y11);
                    __nv_bfloat162 l1 = __floats2bfloat162_rn(y10 - __bfloat162float(h1.x),
                                                              y11 - __bfloat162float(h1.y));
                    *reinterpret_cast<__nv_bfloat162*>(Chi + base0) = h0;
                    *reinterpret_cast<__nv_bfloat162*>(Clo + base0) = l0;
                    *reinterpret_cast<__nv_bfloat162*>(Chi + base1) = h1;
                    *reinterpret_cast<__nv_bfloat162*>(Clo + base1) = l1;
                } else {  // mode 2: transposed [B,H,Dh,T]
                    size_t cb = ((size_t)(b_ * H_SZ + h) * DH_SZ + dh) * T_SZ + t;
                    __nv_bfloat16 h00 = __float2bfloat16(y00);
                    __nv_bfloat16 h01v = __float2bfloat16(y01);
                    __nv_bfloat16 h10 = __float2bfloat16(y10);
                    __nv_bfloat16 h11 = __float2bfloat16(y11);
                    Chi[cb]                = h00;
                    Chi[cb + T_SZ]         = h01v;   // dh+1
                    Chi[cb + 8]            = h10;    // t+8
                    Chi[cb + T_SZ + 8]     = h11;
                    Clo[cb]                = __float2bfloat16(y00 - __bfloat162float(h00));
                    Clo[cb + T_SZ]         = __float2bfloat16(y01 - __bfloat162float(h01v));
                    Clo[cb + 8]            = __float2bfloat16(y10 - __bfloat162float(h10));
                    Clo[cb + T_SZ + 8]     = __float2bfloat16(y11 - __bfloat162float(h11));
                }
            }
        }
    }
}

// ===================== tensor-core flash attention ===========================
// Q tile 128 rows x Dh=128, 8 warps (warp owns 16 rows), K tile 64 keys.
// S and O via bf16x3 m16n8k16; P stays in registers (C-frag == A-frag layout).
// K/V tiles double-buffered in smem via cp.async.
#define AQ_STR 136   // bf16 row stride for Q/K smem
#define AV_STR 72    // bf16 row stride for Vt smem
#define AT_QH  0
#define AT_QL  34816                       // 128*136*2
#define AT_KH  69632                       // 2 bufs x 17408
#define AT_KL  104448
#define AT_VH  139264                      // 2 bufs x 18432
#define AT_VL  176128
#define AT_TOTAL 212992

__device__ __forceinline__ void cp16(uint32_t s, const void* g) {
    asm volatile("cp.async.cg.shared.global [%0], [%1], 16;" :: "r"(s), "l"(g));
}

__device__ __forceinline__ void attn_issue_tiles(
    char* smx, int bh, int kt, int buf, int tid,
    const __nv_bfloat16* khi, const __nv_bfloat16* klo,
    const __nv_bfloat16* vthi, const __nv_bfloat16* vtlo)
{
    // K tile: 64 rows x 128 bf16 = 1024 x 16B per buffer
#pragma unroll
    for (int i = 0; i < 4; i++) {
        int lin = tid + i * 256;
        int r = lin >> 4, c = (lin & 15) * 8;
        size_t gsrc = ((size_t)bh * T_SZ + (size_t)kt * 64 + r) * DH_SZ + c;
        uint32_t sd = (uint32_t)__cvta_generic_to_shared(
            smx + AT_KH + buf * 17408 + r * (AQ_STR * 2) + c * 2);
        cp16(sd, khi + gsrc);
        cp16(sd + (AT_KL - AT_KH), klo + gsrc);
    }
    // Vt tile: 128 rows x 64 bf16 = 1024 x 16B per buffer
#pragma unroll
    for (int i = 0; i < 4; i++) {
        int lin = tid + i * 256;
        int r = lin >> 3, c = (lin & 7) * 8;
        size_t gsrc = ((size_t)bh * DH_SZ + r) * T_SZ + (size_t)kt * 64 + c;
        uint32_t sd = (uint32_t)__cvta_generic_to_shared(
            smx + AT_VH + buf * 18432 + r * (AV_STR * 2) + c * 2);
        cp16(sd, vthi + gsrc);
        cp16(sd + (AT_VL - AT_VH), vtlo + gsrc);
    }
    asm volatile("cp.async.commit_group;");
}

__global__ __launch_bounds__(256, 1)
void attn_mma(const __nv_bfloat16* __restrict__ qhi, const __nv_bfloat16* __restrict__ qlo,
              const __nv_bfloat16* __restrict__ khi, const __nv_bfloat16* __restrict__ klo,
              const __nv_bfloat16* __restrict__ vthi, const __nv_bfloat16* __restrict__ vtlo,
              float* __restrict__ ctx)
{
    extern __shared__ char smx[];
    const int tid  = threadIdx.x;
    const int wid  = tid >> 5;
    const int lane = tid & 31;
    const int gr   = lane >> 2;
    const int qp   = (lane & 3) * 2;
    const int wm   = wid * 16;
    const int bh   = blockIdx.y;
    const int q0   = blockIdx.x * 128;

    // ---- load Q tile (hi/lo) into smem ----
    {
        const __nv_bfloat16* Qh = qhi + ((size_t)bh * T_SZ + q0) * DH_SZ;
        const __nv_bfloat16* Ql = qlo + ((size_t)bh * T_SZ + q0) * DH_SZ;
#pragma unroll
        for (int i = 0; i < 8; i++) {
            int lin = tid + i * 256;
            int r = lin >> 4, c = (lin & 15) * 8;
            *reinterpret_cast<uint4*>(smx + AT_QH + r * (AQ_STR * 2) + c * 2) =
                *reinterpret_cast<const uint4*>(Qh + (size_t)r * DH_SZ + c);
            *reinterpret_cast<uint4*>(smx + AT_QL + r * (AQ_STR * 2) + c * 2) =
                *reinterpret_cast<const uint4*>(Ql + (size_t)r * DH_SZ + c);
        }
    }
    attn_issue_tiles(smx, bh, 0, 0, tid, khi, klo, vthi, vtlo);

    float o[16][4];
#pragma unroll
    for (int n = 0; n < 16; n++)
#pragma unroll
        for (int r = 0; r < 4; r++) o[n][r] = 0.0f;
    float m0 = -INFINITY, m1 = -INFINITY, l0 = 0.0f, l1 = 0.0f;

    for (int kt = 0; kt < T_SZ / 64; kt++) {
        asm volatile("cp.async.wait_group 0;");
        __syncthreads();
        if (kt + 1 < T_SZ / 64)
            attn_issue_tiles(smx, bh, kt + 1, (kt + 1) & 1, tid, khi, klo, vthi, vtlo);

        const char* Kh = smx + AT_KH + (kt & 1) * 17408;
        const char* Kl = smx + AT_KL + (kt & 1) * 17408;
        const char* Vh = smx + AT_VH + (kt & 1) * 18432;
        const char* Vl = smx + AT_VL + (kt & 1) * 18432;

        // ---- S = Q * K^T : 8 atoms (64 keys), 8 k-steps (Dh=128), bf16x3 ----
        float s4[8][4];
#pragma unroll
        for (int a = 0; a < 8; a++)
#pragma unroll
            for (int r = 0; r < 4; r++) s4[a][r] = 0.0f;

#pragma unroll
        for (int kk = 0; kk < 8; kk++) {
            const int kb = kk * 16;
            const char* q0p = smx + AT_QH + ((wm + gr) * AQ_STR + kb + qp) * 2;
            const char* q1p = smx + AT_QL + ((wm + gr) * AQ_STR + kb + qp) * 2;
            uint32_t aH0 = *reinterpret_cast<const uint32_t*>(q0p);
            uint32_t aH1 = *reinterpret_cast<const uint32_t*>(q0p + 8 * AQ_STR * 2);
            uint32_t aH2 = *reinterpret_cast<const uint32_t*>(q0p + 16);
            uint32_t aH3 = *reinterpret_cast<const uint32_t*>(q0p + 8 * AQ_STR * 2 + 16);
            uint32_t aL0 = *reinterpret_cast<const uint32_t*>(q1p);
            uint32_t aL1 = *reinterpret_cast<const uint32_t*>(q1p + 8 * AQ_STR * 2);
            uint32_t aL2 = *reinterpret_cast<const uint32_t*>(q1p + 16);
            uint32_t aL3 = *reinterpret_cast<const uint32_t*>(q1p + 8 * AQ_STR * 2 + 16);
#pragma unroll
            for (int a = 0; a < 8; a++) {
                const char* kp = Kh + ((a * 8 + gr) * AQ_STR + kb + qp) * 2;
                const char* lp = Kl + ((a * 8 + gr) * AQ_STR + kb + qp) * 2;
                uint32_t bH0 = *reinterpret_cast<const uint32_t*>(kp);
                uint32_t bH1 = *reinterpret_cast<const uint32_t*>(kp + 16);
                uint32_t bL0 = *reinterpret_cast<const uint32_t*>(lp);
                uint32_t bL1 = *reinterpret_cast<const uint32_t*>(lp + 16);
                MMA_BF16(s4[a], aH0, aH1, aH2, aH3, bH0, bH1);
                MMA_BF16(s4[a], aH0, aH1, aH2, aH3, bL0, bL1);
                MMA_BF16(s4[a], aL0, aL1, aL2, aL3, bH0, bH1);
            }
        }

        // ---- online softmax (rows gr and gr+8 of warp stripe) ----
        float mx0 = -INFINITY, mx1 = -INFINITY;
#pragma unroll
        for (int a = 0; a < 8; a++) {
            mx0 = fmaxf(mx0, fmaxf(s4[a][0], s4[a][1]));
            mx1 = fmaxf(mx1, fmaxf(s4[a][2], s4[a][3]));
        }
        mx0 = fmaxf(mx0, __shfl_xor_sync(0xffffffffu, mx0, 1));
        mx0 = fmaxf(mx0, __shfl_xor_sync(0xffffffffu, mx0, 2));
        mx1 = fmaxf(mx1, __shfl_xor_sync(0xffffffffu, mx1, 1));
        mx1 = fmaxf(mx1, __shfl_xor_sync(0xffffffffu, mx1, 2));
        float mn0 = fmaxf(m0, mx0), mn1 = fmaxf(m1, mx1);
        float al0 = __expf(m0 - mn0), al1 = __expf(m1 - mn1);
        m0 = mn0; m1 = mn1;
        float rs0 = 0.0f, rs1 = 0.0f;
#pragma unroll
        for (int a = 0; a < 8; a++) {
            s4[a][0] = __expf(s4[a][0] - mn0);
            s4[a][1] = __expf(s4[a][1] - mn0);
            s4[a][2] = __expf(s4[a][2] - mn1);
            s4[a][3] = __expf(s4[a][3] - mn1);
            rs0 += s4[a][0] + s4[a][1];
            rs1 += s4[a][2] + s4[a][3];
        }
        rs0 += __shfl_xor_sync(0xffffffffu, rs0, 1);
        rs0 += __shfl_xor_sync(0xffffffffu, rs0, 2);
        rs1 += __shfl_xor_sync(0xffffffffu, rs1, 1);
        rs1 += __shfl_xor_sync(0xffffffffu, rs1, 2);
        l0 = l0 * al0 + rs0;
        l1 = l1 * al1 + rs1;
#pragma unroll
        for (int n = 0; n < 16; n++) {
            o[n][0] *= al0; o[n][1] *= al0;
            o[n][2] *= al1; o[n][3] *= al1;
        }

        // ---- pack P into A-fragments (C-frag layout == A-frag layout) ----
        uint32_t pH[4][4], pL[4][4];
#pragma unroll
        for (int t = 0; t < 4; t++) {
            int a = 2 * t, b2 = 2 * t + 1;
            __nv_bfloat162 h;
            h = __floats2bfloat162_rn(s4[a][0], s4[a][1]);
            pH[t][0] = *reinterpret_cast<uint32_t*>(&h);
            __nv_bfloat162 l = __floats2bfloat162_rn(s4[a][0] - __bfloat162float(h.x),
                                                     s4[a][1] - __bfloat162float(h.y));
            pL[t][0] = *reinterpret_cast<uint32_t*>(&l);
            h = __floats2bfloat162_rn(s4[a][2], s4[a][3]);
            pH[t][1] = *reinterpret_cast<uint32_t*>(&h);
            l = __floats2bfloat162_rn(s4[a][2] - __bfloat162float(h.x),
                                      s4[a][3] - __bfloat162float(h.y));
            pL[t][1] = *reinterpret_cast<uint32_t*>(&l);
            h = __floats2bfloat162_rn(s4[b2][0], s4[b2][1]);
            pH[t][2] = *reinterpret_cast<uint32_t*>(&h);
            l = __floats2bfloat162_rn(s4[b2][0] - __bfloat162float(h.x),
                                      s4[b2][1] - __bfloat162float(h.y));
            pL[t][2] = *reinterpret_cast<uint32_t*>(&l);
            h = __floats2bfloat162_rn(s4[b2][2], s4[b2][3]);
            pH[t][3] = *reinterpret_cast<uint32_t*>(&h);
            l = __floats2bfloat162_rn(s4[b2][2] - __bfloat162float(h.x),
                                      s4[b2][3] - __bfloat162float(h.y));
            pL[t][3] = *reinterpret_cast<uint32_t*>(&l);
        }

        // ---- O += P * V : 16 n-atoms (Dh), 4 k-steps (64 keys), bf16x3 ----
#pragma unroll
        for (int n = 0; n < 16; n++) {
            const int nr = n * 8 + gr;
#pragma unroll
            for (int t = 0; t < 4; t++) {
                const char* vp = Vh + (nr * AV_STR + t * 16 + qp) * 2;
                const char* wp = Vl + (nr * AV_STR + t * 16 + qp) * 2;
                uint32_t bH0 = *reinterpret_cast<const uint32_t*>(vp);
                uint32_t bH1 = *reinterpret_cast<const uint32_t*>(vp + 16);
                uint32_t bL0 = *reinterpret_cast<const uint32_t*>(wp);
                uint32_t bL1 = *reinterpret_cast<const uint32_t*>(wp + 16);
                MMA_BF16(o[n], pH[t][0], pH[t][1], pH[t][2], pH[t][3], bH0, bH1);
                MMA_BF16(o[n], pH[t][0], pH[t][1], pH[t][2], pH[t][3], bL0, bL1);
                MMA_BF16(o[n], pL[t][0], pL[t][1], pL[t][2], pL[t][3], bH0, bH1);
            }
        }
    }

    // ---- epilogue: normalize, write ctx[b, t, h*128 + d] ----
    const float inv0 = 1.0f / l0;
    const float inv1 = 1.0f / l1;
    const int b_ = bh >> 4;
    const int h  = bh & 15;
    const int t0g = q0 + wm + gr;
    float* dst0 = ctx + ((size_t)(b_ * T_SZ + t0g)) * D_SZ + h * DH_SZ;
    float* dst1 = dst0 + (size_t)8 * D_SZ;
#pragma unroll
    for (int n = 0; n < 16; n++) {
        int d = n * 8 + qp;
        float2 r0; r0.x = o[n][0] * inv0; r0.y = o[n][1] * inv0;
        float2 r1; r1.x = o[n][2] * inv1; r1.y = o[n][3] * inv1;
        *reinterpret_cast<float2*>(dst0 + d) = r0;
        *reinterpret_cast<float2*>(dst1 + d) = r1;
    }
}

// ================================ launch =====================================
extern "C" void kernel_launch(void* const* d_in, const int* in_sizes, int n_in,
                              void* d_out, int out_size)
{
    (void)in_sizes; (void)n_in; (void)out_size;
    const float* x  = (const float*)d_in[0];
    const float* Wq = (const float*)d_in[1];
    const float* bq = (const float*)d_in[2];
    const float* Wk = (const float*)d_in[3];
    const float* bk = (const float*)d_in[4];
    const float* Wv = (const float*)d_in[5];
    const float* bv = (const float*)d_in[6];
    const float* Wo = (const float*)d_in[7];
    const float* bo = (const float*)d_in[8];
    float* out = (float*)d_out;

    float* ctx;
    __nv_bfloat16 *ahi, *alo, *whi, *wlo, *qh, *ql, *kh, *kl, *vh, *vl;
    cudaGetSymbolAddress((void**)&ctx, g_ctx);
    cudaGetSymbolAddress((void**)&ahi, g_ahi);
    cudaGetSymbolAddress((void**)&alo, g_alo);
    cudaGetSymbolAddress((void**)&whi, g_whi);
    cudaGetSymbolAddress((void**)&wlo, g_wlo);
    cudaGetSymbolAddress((void**)&qh,  g_qhi);
    cudaGetSymbolAddress((void**)&ql,  g_qlo);
    cudaGetSymbolAddress((void**)&kh,  g_khi);
    cudaGetSymbolAddress((void**)&kl,  g_klo);
    cudaGetSymbolAddress((void**)&vh,  g_vthi);
    cudaGetSymbolAddress((void**)&vl,  g_vtlo);

    cudaFuncSetAttribute(attn_mma,
                         cudaFuncAttributeMaxDynamicSharedMemorySize, AT_TOTAL);

    const int nx4 = M_ROWS * D_SZ / 4;
    const int nw4 = D_SZ * D_SZ / 4;
    dim3 ggrid(D_SZ / GBN, M_ROWS / GBM);   // 16 x 64
    const float qscale = 0.08838834764831845f;   // 1/sqrt(128)

    split_bf16<<<(nx4 + 255) / 256, 256>>>(x, ahi, alo, nx4);

    split_bf16<<<(nw4 + 255) / 256, 256>>>(Wq, whi, wlo, nw4);
    gemm_mma<<<ggrid, 256>>>(ahi, alo, whi, wlo, bq, nullptr, qh, ql, 1, qscale);
    split_bf16<<<(nw4 + 255) / 256, 256>>>(Wk, whi, wlo, nw4);
    gemm_mma<<<ggrid, 256>>>(ahi, alo, whi, wlo, bk, nullptr, kh, kl, 1, 1.0f);
    split_bf16<<<(nw4 + 255) / 256, 256>>>(Wv, whi, wlo, nw4);
    gemm_mma<<<ggrid, 256>>>(ahi, alo, whi, wlo, bv, nullptr, vh, vl, 2, 1.0f);

    dim3 agrid(T_SZ / 128, B_SZ * H_SZ);    // 16 x 64
    attn_mma<<<agrid, 256, AT_TOTAL>>>(qh, ql, kh, kl, vh, vl, ctx);

    split_bf16<<<(nx4 + 255) / 256, 256>>>(ctx, ahi, alo, nx4);
    split_bf16<<<(nw4 + 255) / 256, 256>>>(Wo, whi, wlo, nw4);
    gemm_mma<<<ggrid, 256>>>(ahi, alo, whi, wlo, bo, out, nullptr, nullptr, 0, 1.0f);
}